// round 1
// baseline (speedup 1.0000x reference)
#include <cuda_runtime.h>
#include <cuda_bf16.h>
#include <math.h>

#define NND   65536          // nodes
#define EE    262144         // edges (before self loops)
#define E2    (EE + NND)     // edges with self loops = 327680
#define BB    2048           // graphs
#define HH    4              // heads
#define DD    192            // per-head dim
#define HID   768
#define LLAY  2
#define EPSL  1e-5f
#define NSLOPE 0.2f

// ---------------- scratch (device globals; no allocations allowed) ----------
__device__ float g_xw[(size_t)NND * HID];
__device__ float g_h1[(size_t)NND * HID];
__device__ float g_h2[(size_t)NND * HID];
__device__ float g_asrc[NND * HH];
__device__ float g_adst[NND * HH];
__device__ int   g_deg[NND];
__device__ int   g_rowptr[NND + 1];
__device__ int   g_wptr[NND];
__device__ int   g_esrc[E2];
__device__ int   g_off[BB + 1];
__device__ float g_pool[BB * HID];

// ---------------- CSR build --------------------------------------------------
__global__ void zero_deg_kernel(int* deg) {
    int i = blockIdx.x * blockDim.x + threadIdx.x;
    if (i < NND) deg[i] = 0;
}

__global__ void count_deg_kernel(const int* __restrict__ ei, int* deg) {
    int e = blockIdx.x * blockDim.x + threadIdx.x;
    if (e >= E2) return;
    int dst = (e < EE) ? ei[EE + e] : (e - EE);
    atomicAdd(&deg[dst], 1);
}

__global__ void scan_deg_kernel(const int* __restrict__ deg, int* rowptr, int* wptr) {
    __shared__ int part[1024];
    int tid = threadIdx.x;
    const int CH = NND / 1024;   // 64
    int base = tid * CH;
    int s = 0;
#pragma unroll 8
    for (int i = 0; i < CH; i++) s += deg[base + i];
    part[tid] = s;
    __syncthreads();
    for (int off = 1; off < 1024; off <<= 1) {
        int v = 0;
        if (tid >= off) v = part[tid - off];
        __syncthreads();
        if (tid >= off) part[tid] += v;
        __syncthreads();
    }
    int run = (tid == 0) ? 0 : part[tid - 1];
    for (int i = 0; i < CH; i++) {
        rowptr[base + i] = run;
        wptr[base + i]   = run;
        run += deg[base + i];
    }
    if (tid == 1023) rowptr[NND] = run;
}

__global__ void fill_src_kernel(const int* __restrict__ ei, int* wptr, int* esrc) {
    int e = blockIdx.x * blockDim.x + threadIdx.x;
    if (e >= E2) return;
    int src, dst;
    if (e < EE) { src = ei[e]; dst = ei[EE + e]; }
    else        { src = e - EE; dst = e - EE; }
    int p = atomicAdd(&wptr[dst], 1);
    esrc[p] = src;
}

// ---------------- SGEMM: C[M,768] = A[M,768] @ B[768,768] (+bias) ------------
// BM=BN=128, BK=8, 256 threads, 8x8 micro-tile, double-buffered SMEM.
__global__ __launch_bounds__(256, 2)
void sgemm768_kernel(const float* __restrict__ A, const float* __restrict__ Bm,
                     const float* __restrict__ bias, float* __restrict__ C) {
    const int K = HID;
    __shared__ float As[2][8][132];
    __shared__ float Bs[2][8][128];
    int tid  = threadIdx.x;
    int brow = blockIdx.y * 128;
    int bcol = blockIdx.x * 128;
    int tx = tid & 15, ty = tid >> 4;
    int arow = tid >> 1;        // 0..127
    int acol = (tid & 1) * 4;   // 0 or 4
    int brw  = tid >> 5;        // 0..7
    int bcl  = (tid & 31) * 4;  // 0..124

    float acc[8][8];
#pragma unroll
    for (int i = 0; i < 8; i++)
#pragma unroll
        for (int j = 0; j < 8; j++) acc[i][j] = 0.f;

    float4 ra = *reinterpret_cast<const float4*>(A + (size_t)(brow + arow) * K + acol);
    float4 rb = *reinterpret_cast<const float4*>(Bm + (size_t)brw * HID + bcol + bcl);
    As[0][acol + 0][arow] = ra.x;
    As[0][acol + 1][arow] = ra.y;
    As[0][acol + 2][arow] = ra.z;
    As[0][acol + 3][arow] = ra.w;
    *reinterpret_cast<float4*>(&Bs[0][brw][bcl]) = rb;
    __syncthreads();

    int cur = 0;
    const int KT = K / 8;  // 96
    for (int kt = 0; kt < KT; kt++) {
        if (kt < KT - 1) {
            int k0 = (kt + 1) * 8;
            ra = *reinterpret_cast<const float4*>(A + (size_t)(brow + arow) * K + k0 + acol);
            rb = *reinterpret_cast<const float4*>(Bm + (size_t)(k0 + brw) * HID + bcol + bcl);
        }
#pragma unroll
        for (int k = 0; k < 8; k++) {
            float af[8], bf[8];
            float4 a0 = *reinterpret_cast<const float4*>(&As[cur][k][ty * 8]);
            float4 a1 = *reinterpret_cast<const float4*>(&As[cur][k][ty * 8 + 4]);
            float4 b0 = *reinterpret_cast<const float4*>(&Bs[cur][k][tx * 8]);
            float4 b1 = *reinterpret_cast<const float4*>(&Bs[cur][k][tx * 8 + 4]);
            af[0]=a0.x; af[1]=a0.y; af[2]=a0.z; af[3]=a0.w;
            af[4]=a1.x; af[5]=a1.y; af[6]=a1.z; af[7]=a1.w;
            bf[0]=b0.x; bf[1]=b0.y; bf[2]=b0.z; bf[3]=b0.w;
            bf[4]=b1.x; bf[5]=b1.y; bf[6]=b1.z; bf[7]=b1.w;
#pragma unroll
            for (int i = 0; i < 8; i++)
#pragma unroll
                for (int j = 0; j < 8; j++)
                    acc[i][j] = fmaf(af[i], bf[j], acc[i][j]);
        }
        if (kt < KT - 1) {
            int nb = cur ^ 1;
            As[nb][acol + 0][arow] = ra.x;
            As[nb][acol + 1][arow] = ra.y;
            As[nb][acol + 2][arow] = ra.z;
            As[nb][acol + 3][arow] = ra.w;
            *reinterpret_cast<float4*>(&Bs[nb][brw][bcl]) = rb;
            __syncthreads();
            cur = nb;
        }
    }

#pragma unroll
    for (int i = 0; i < 8; i++) {
        int r = brow + ty * 8 + i;
#pragma unroll
        for (int j = 0; j < 8; j += 4) {
            int c = bcol + tx * 8 + j;
            float4 v;
            v.x = acc[i][j + 0]; v.y = acc[i][j + 1];
            v.z = acc[i][j + 2]; v.w = acc[i][j + 3];
            if (bias) {
                v.x += bias[c + 0]; v.y += bias[c + 1];
                v.z += bias[c + 2]; v.w += bias[c + 3];
            }
            *reinterpret_cast<float4*>(C + (size_t)r * HID + c) = v;
        }
    }
}

// ---------------- alpha projections ------------------------------------------
// one warp per (node, head): asrc[n,h] = <xw[n,h,:], att_src[h,:]>, same for dst
__global__ void alpha_kernel(const float* __restrict__ xw,
                             const float* __restrict__ a_s,
                             const float* __restrict__ a_d,
                             float* __restrict__ asrc, float* __restrict__ adst) {
    int gw = blockIdx.x * (blockDim.x >> 5) + (threadIdx.x >> 5);
    if (gw >= NND * HH) return;
    int t = threadIdx.x & 31;
    int n = gw >> 2, h = gw & 3;
    const float* row = xw + (size_t)n * HID + h * DD;
    const float* vs = a_s + h * DD;
    const float* vd = a_d + h * DD;
    float ss = 0.f, sd = 0.f;
#pragma unroll
    for (int k = 0; k < 6; k++) {
        float v = row[t + 32 * k];
        ss = fmaf(v, vs[t + 32 * k], ss);
        sd = fmaf(v, vd[t + 32 * k], sd);
    }
#pragma unroll
    for (int o = 16; o; o >>= 1) {
        ss += __shfl_xor_sync(0xffffffffu, ss, o);
        sd += __shfl_xor_sync(0xffffffffu, sd, o);
    }
    if (t == 0) {
        asrc[n * HH + h] = ss;
        adst[n * HH + h] = sd;
    }
}

__device__ __forceinline__ float lrelu(float x) {
    return x > 0.f ? x : NSLOPE * x;
}

// ---------------- fused attention aggregation + bias + LN + ReLU + residual --
// one warp per destination node; 24 accumulator regs per thread cover all 768 dims
__global__ __launch_bounds__(256)
void agg_kernel(const int* __restrict__ rowptr, const int* __restrict__ esrc,
                const float* __restrict__ asrc, const float* __restrict__ adst,
                const float* __restrict__ xw, const float* __restrict__ h_in,
                const float* __restrict__ bias, const float* __restrict__ gamma,
                const float* __restrict__ beta, float* __restrict__ h_out) {
    int i = blockIdx.x * (blockDim.x >> 5) + (threadIdx.x >> 5);
    if (i >= NND) return;
    int t = threadIdx.x & 31;

    float4 ad = reinterpret_cast<const float4*>(adst)[i];
    int beg = rowptr[i], end = rowptr[i + 1];

    // pass 1: per-head max logit
    float m0 = -1e30f, m1 = -1e30f, m2 = -1e30f, m3 = -1e30f;
    for (int b0 = beg; b0 < end; b0 += 32) {
        int e = b0 + t;
        float l0 = -1e30f, l1 = -1e30f, l2 = -1e30f, l3 = -1e30f;
        if (e < end) {
            int j = esrc[e];
            float4 as = reinterpret_cast<const float4*>(asrc)[j];
            l0 = lrelu(as.x + ad.x); l1 = lrelu(as.y + ad.y);
            l2 = lrelu(as.z + ad.z); l3 = lrelu(as.w + ad.w);
        }
        m0 = fmaxf(m0, l0); m1 = fmaxf(m1, l1);
        m2 = fmaxf(m2, l2); m3 = fmaxf(m3, l3);
    }
#pragma unroll
    for (int o = 16; o; o >>= 1) {
        m0 = fmaxf(m0, __shfl_xor_sync(0xffffffffu, m0, o));
        m1 = fmaxf(m1, __shfl_xor_sync(0xffffffffu, m1, o));
        m2 = fmaxf(m2, __shfl_xor_sync(0xffffffffu, m2, o));
        m3 = fmaxf(m3, __shfl_xor_sync(0xffffffffu, m3, o));
    }

    // pass 2: exp weights, denominators, weighted feature gather
    float acc[24];
#pragma unroll
    for (int k = 0; k < 24; k++) acc[k] = 0.f;
    float d0 = 0.f, d1 = 0.f, d2 = 0.f, d3 = 0.f;

    for (int b0 = beg; b0 < end; b0 += 32) {
        int e = b0 + t;
        int j = 0;
        float e0 = 0.f, e1 = 0.f, e2 = 0.f, e3 = 0.f;
        if (e < end) {
            j = esrc[e];
            float4 as = reinterpret_cast<const float4*>(asrc)[j];
            e0 = expf(lrelu(as.x + ad.x) - m0);
            e1 = expf(lrelu(as.y + ad.y) - m1);
            e2 = expf(lrelu(as.z + ad.z) - m2);
            e3 = expf(lrelu(as.w + ad.w) - m3);
        }
        d0 += e0; d1 += e1; d2 += e2; d3 += e3;
        int cnt = min(32, end - b0);
        for (int q = 0; q < cnt; q++) {
            int   jq = __shfl_sync(0xffffffffu, j,  q);
            float w0 = __shfl_sync(0xffffffffu, e0, q);
            float w1 = __shfl_sync(0xffffffffu, e1, q);
            float w2 = __shfl_sync(0xffffffffu, e2, q);
            float w3 = __shfl_sync(0xffffffffu, e3, q);
            const float* row = xw + (size_t)jq * HID;
#pragma unroll
            for (int k = 0; k < 24; k++) {
                float wk = (k < 6) ? w0 : (k < 12) ? w1 : (k < 18) ? w2 : w3;
                acc[k] = fmaf(wk, row[t + 32 * k], acc[k]);
            }
        }
    }
#pragma unroll
    for (int o = 16; o; o >>= 1) {
        d0 += __shfl_xor_sync(0xffffffffu, d0, o);
        d1 += __shfl_xor_sync(0xffffffffu, d1, o);
        d2 += __shfl_xor_sync(0xffffffffu, d2, o);
        d3 += __shfl_xor_sync(0xffffffffu, d3, o);
    }
    float i0 = 1.f / d0, i1 = 1.f / d1, i2 = 1.f / d2, i3 = 1.f / d3;

    // normalize + bias; then LayerNorm across the 768 dims held by the warp
    float s = 0.f;
#pragma unroll
    for (int k = 0; k < 24; k++) {
        float ik = (k < 6) ? i0 : (k < 12) ? i1 : (k < 18) ? i2 : i3;
        float v = acc[k] * ik + bias[t + 32 * k];
        acc[k] = v;
        s += v;
    }
#pragma unroll
    for (int o = 16; o; o >>= 1) s += __shfl_xor_sync(0xffffffffu, s, o);
    float mu = s * (1.f / HID);
    float vs = 0.f;
#pragma unroll
    for (int k = 0; k < 24; k++) {
        float dlt = acc[k] - mu;
        vs = fmaf(dlt, dlt, vs);
    }
#pragma unroll
    for (int o = 16; o; o >>= 1) vs += __shfl_xor_sync(0xffffffffu, vs, o);
    float rstd = rsqrtf(vs * (1.f / HID) + EPSL);

    const float* hrow = h_in + (size_t)i * HID;
    float* orow = h_out + (size_t)i * HID;
#pragma unroll
    for (int k = 0; k < 24; k++) {
        int d = t + 32 * k;
        float v = (acc[k] - mu) * rstd * gamma[d] + beta[d];
        v = fmaxf(v, 0.f) + hrow[d];
        orow[d] = v;
    }
}

// ---------------- graph pooling ----------------------------------------------
__global__ void graph_off_kernel(const int* __restrict__ bvec, int* off) {
    int b = blockIdx.x * blockDim.x + threadIdx.x;
    if (b > BB) return;
    int lo = 0, hi = NND;
    while (lo < hi) {
        int mid = (lo + hi) >> 1;
        if (bvec[mid] < b) lo = mid + 1; else hi = mid;
    }
    off[b] = lo;
}

__global__ void pool_kernel(const float* __restrict__ h, const int* __restrict__ off,
                            float* __restrict__ pooled) {
    int b = blockIdx.x;
    int t = threadIdx.x;  // 256
    int s = off[b], e = off[b + 1];
    float a0 = 0.f, a1 = 0.f, a2 = 0.f;
    for (int n = s; n < e; n++) {
        const float* r = h + (size_t)n * HID;
        a0 += r[t];
        a1 += r[t + 256];
        a2 += r[t + 512];
    }
    float inv = 1.f / fmaxf((float)(e - s), 1.f);
    pooled[b * HID + t]       = a0 * inv;
    pooled[b * HID + t + 256] = a1 * inv;
    pooled[b * HID + t + 512] = a2 * inv;
}

// ---------------- launch -----------------------------------------------------
extern "C" void kernel_launch(void* const* d_in, const int* in_sizes, int n_in,
                              void* d_out, int out_size) {
    const float* x      = (const float*)d_in[0];
    const int*   ei     = (const int*)d_in[1];
    const int*   bvec   = (const int*)d_in[2];
    const float* W      = (const float*)d_in[3];
    const float* attS   = (const float*)d_in[4];
    const float* attD   = (const float*)d_in[5];
    const float* bias   = (const float*)d_in[6];
    const float* gamma  = (const float*)d_in[7];
    const float* beta   = (const float*)d_in[8];
    const float* out_w  = (const float*)d_in[9];
    const float* out_b  = (const float*)d_in[10];
    float* out = (float*)d_out;

    float *xw, *h1, *h2, *asrc, *adst, *pool;
    int *deg, *rowptr, *wptr, *esrc, *off;
    cudaGetSymbolAddress((void**)&xw,    g_xw);
    cudaGetSymbolAddress((void**)&h1,    g_h1);
    cudaGetSymbolAddress((void**)&h2,    g_h2);
    cudaGetSymbolAddress((void**)&asrc,  g_asrc);
    cudaGetSymbolAddress((void**)&adst,  g_adst);
    cudaGetSymbolAddress((void**)&deg,   g_deg);
    cudaGetSymbolAddress((void**)&rowptr,g_rowptr);
    cudaGetSymbolAddress((void**)&wptr,  g_wptr);
    cudaGetSymbolAddress((void**)&esrc,  g_esrc);
    cudaGetSymbolAddress((void**)&off,   g_off);
    cudaGetSymbolAddress((void**)&pool,  g_pool);

    // CSR build (dst -> list of src, self loops included)
    zero_deg_kernel<<<NND / 256, 256>>>(deg);
    count_deg_kernel<<<(E2 + 255) / 256, 256>>>(ei, deg);
    scan_deg_kernel<<<1, 1024>>>(deg, rowptr, wptr);
    fill_src_kernel<<<(E2 + 255) / 256, 256>>>(ei, wptr, esrc);

    dim3 gBig(HID / 128, NND / 128);   // (6, 512)
    int alphaBlocks = (NND * HH) / 8;  // 32768
    int aggBlocks   = NND / 8;         // 8192

    // layer 0
    sgemm768_kernel<<<gBig, 256>>>(x, W, nullptr, xw);
    alpha_kernel<<<alphaBlocks, 256>>>(xw, attS, attD, asrc, adst);
    agg_kernel<<<aggBlocks, 256>>>(rowptr, esrc, asrc, adst, xw, x,
                                   bias, gamma, beta, h1);
    // layer 1
    sgemm768_kernel<<<gBig, 256>>>(h1, W + HID * HID, nullptr, xw);
    alpha_kernel<<<alphaBlocks, 256>>>(xw, attS + HH * DD, attD + HH * DD, asrc, adst);
    agg_kernel<<<aggBlocks, 256>>>(rowptr, esrc, asrc, adst, xw, h1,
                                   bias + HID, gamma + HID, beta + HID, h2);

    // global mean pool + output projection
    graph_off_kernel<<<(BB + 1 + 255) / 256, 256>>>(bvec, off);
    pool_kernel<<<BB, 256>>>(h2, off, pool);
    dim3 gOut(HID / 128, BB / 128);    // (6, 16)
    sgemm768_kernel<<<gOut, 256>>>(pool, out_w, out_b, out);
}

// round 8
// speedup vs baseline: 1.6752x; 1.6752x over previous
#include <cuda_runtime.h>
#include <cuda_bf16.h>
#include <math.h>
#include <stdint.h>

#define NND   65536          // nodes
#define EE    262144         // edges (before self loops)
#define E2    (EE + NND)     // edges with self loops = 327680
#define BB    2048           // graphs
#define HH    4              // heads
#define DD    192            // per-head dim
#define HID   768
#define EPSL  1e-5f
#define NSLOPE 0.2f

// ===================== PTX helpers (base-target legal) =======================
__device__ __forceinline__ uint32_t smem_u32(const void* p) {
    uint32_t a;
    asm("{ .reg .u64 t; cvta.to.shared.u64 t, %1; cvt.u32.u64 %0, t; }"
        : "=r"(a) : "l"(p));
    return a;
}
#define CP_ASYNC16(sa, gp) \
    asm volatile("cp.async.cg.shared.global [%0], [%1], 16;" :: "r"(sa), "l"(gp))
#define CP_COMMIT() asm volatile("cp.async.commit_group;" ::: "memory")
#define CP_WAIT(n)  asm volatile("cp.async.wait_group %0;" :: "n"(n) : "memory")

#define LDSM_X4(r0, r1, r2, r3, a) \
    asm volatile("ldmatrix.sync.aligned.m8n8.x4.shared.b16 {%0,%1,%2,%3}, [%4];" \
                 : "=r"(r0), "=r"(r1), "=r"(r2), "=r"(r3) : "r"(a))

#define MMA16816(c, a, b0, b1) \
    asm volatile("mma.sync.aligned.m16n8k16.row.col.f32.bf16.bf16.f32 " \
                 "{%0,%1,%2,%3}, {%4,%5,%6,%7}, {%8,%9}, {%0,%1,%2,%3};" \
                 : "+f"((c)[0]), "+f"((c)[1]), "+f"((c)[2]), "+f"((c)[3]) \
                 : "r"((a)[0]), "r"((a)[1]), "r"((a)[2]), "r"((a)[3]), \
                   "r"(b0), "r"(b1))

// ===================== scratch (device globals) ==============================
__device__ float g_xw[(size_t)NND * HID];
__device__ float g_h1[(size_t)NND * HID];
__device__ float g_h2[(size_t)NND * HID];
__device__ __align__(16) __nv_bfloat16 g_ah[(size_t)NND * HID];
__device__ __align__(16) __nv_bfloat16 g_al[(size_t)NND * HID];
__device__ __align__(16) __nv_bfloat16 g_wth[3 * HID * HID];  // W0^T, W1^T, out_w^T (hi)
__device__ __align__(16) __nv_bfloat16 g_wtl[3 * HID * HID];  // (lo)
__device__ float g_asrc[NND * HH];
__device__ float g_adst[NND * HH];
__device__ int   g_deg[NND];
__device__ int   g_rowptr[NND + 1];
__device__ int   g_wptr[NND];
__device__ int   g_esrc[E2];
__device__ int   g_off[BB + 1];
__device__ float g_pool[BB * HID];

// ===================== CSR build ============================================
__global__ void zero_deg_kernel(int* deg) {
    int i = blockIdx.x * blockDim.x + threadIdx.x;
    if (i < NND) deg[i] = 0;
}
__global__ void count_deg_kernel(const int* __restrict__ ei, int* deg) {
    int e = blockIdx.x * blockDim.x + threadIdx.x;
    if (e >= E2) return;
    int dst = (e < EE) ? ei[EE + e] : (e - EE);
    atomicAdd(&deg[dst], 1);
}
__global__ void scan_deg_kernel(const int* __restrict__ deg, int* rowptr, int* wptr) {
    __shared__ int part[1024];
    int tid = threadIdx.x;
    const int CH = NND / 1024;
    int base = tid * CH;
    int s = 0;
#pragma unroll 8
    for (int i = 0; i < CH; i++) s += deg[base + i];
    part[tid] = s;
    __syncthreads();
    for (int off = 1; off < 1024; off <<= 1) {
        int v = 0;
        if (tid >= off) v = part[tid - off];
        __syncthreads();
        if (tid >= off) part[tid] += v;
        __syncthreads();
    }
    int run = (tid == 0) ? 0 : part[tid - 1];
    for (int i = 0; i < CH; i++) {
        rowptr[base + i] = run;
        wptr[base + i]   = run;
        run += deg[base + i];
    }
    if (tid == 1023) rowptr[NND] = run;
}
__global__ void fill_src_kernel(const int* __restrict__ ei, int* wptr, int* esrc) {
    int e = blockIdx.x * blockDim.x + threadIdx.x;
    if (e >= E2) return;
    int src, dst;
    if (e < EE) { src = ei[e]; dst = ei[EE + e]; }
    else        { src = e - EE; dst = e - EE; }
    int p = atomicAdd(&wptr[dst], 1);
    esrc[p] = src;
}

// ===================== fp32 -> bf16 hi/lo conversions ========================
__global__ void convert_hilo_kernel(const float* __restrict__ in,
                                    __nv_bfloat16* __restrict__ hi,
                                    __nv_bfloat16* __restrict__ lo, int n4) {
    int i = blockIdx.x * blockDim.x + threadIdx.x;
    if (i >= n4) return;
    float4 v = reinterpret_cast<const float4*>(in)[i];
    __nv_bfloat16 h0 = __float2bfloat16(v.x);
    __nv_bfloat16 h1 = __float2bfloat16(v.y);
    __nv_bfloat16 h2 = __float2bfloat16(v.z);
    __nv_bfloat16 h3 = __float2bfloat16(v.w);
    __nv_bfloat162* H = reinterpret_cast<__nv_bfloat162*>(hi);
    H[2 * i]     = __halves2bfloat162(h0, h1);
    H[2 * i + 1] = __halves2bfloat162(h2, h3);
    __nv_bfloat162* L = reinterpret_cast<__nv_bfloat162*>(lo);
    L[2 * i]     = __halves2bfloat162(__float2bfloat16(v.x - __bfloat162float(h0)),
                                      __float2bfloat16(v.y - __bfloat162float(h1)));
    L[2 * i + 1] = __halves2bfloat162(__float2bfloat16(v.z - __bfloat162float(h2)),
                                      __float2bfloat16(v.w - __bfloat162float(h3)));
}

// transpose + split: th[n*768+k] = bf16(W[k*768+n]), tl = residual
__global__ void wtrans_kernel(const float* __restrict__ W,
                              __nv_bfloat16* __restrict__ th,
                              __nv_bfloat16* __restrict__ tl) {
    __shared__ float t[32][33];
    int n0 = blockIdx.x * 32, k0 = blockIdx.y * 32;
    int tx = threadIdx.x, ty0 = threadIdx.y;
#pragma unroll
    for (int dy = 0; dy < 32; dy += 8)
        t[ty0 + dy][tx] = W[(size_t)(k0 + ty0 + dy) * HID + n0 + tx];
    __syncthreads();
#pragma unroll
    for (int dy = 0; dy < 32; dy += 8) {
        float v = t[tx][ty0 + dy];
        int n = n0 + ty0 + dy, k = k0 + tx;
        __nv_bfloat16 h = __float2bfloat16(v);
        th[(size_t)n * HID + k] = h;
        tl[(size_t)n * HID + k] = __float2bfloat16(v - __bfloat162float(h));
    }
}

// ===================== mma.sync bf16x3 GEMM ==================================
// C[M,768] = A[M,768] @ Wt^T (+bias), Wt K-major [768(N),768(K)].
// A = Ah+Al, W = Wh+Wl (bf16); acc fp32 of AhWh + AhWl + AlWh.
// Tile 128x128x32, 4-stage cp.async pipeline, 8 warps, warp tile 64x32.
#define BKG   32
#define KTN   (HID / BKG)      // 24
#define RS    40               // smem row stride in bf16 (80 bytes)
#define MAT_BYTES (128 * RS * 2)        // 10240
#define OFF_AH 0
#define OFF_AL (MAT_BYTES)
#define OFF_BH (2 * MAT_BYTES)
#define OFF_BL (3 * MAT_BYTES)
#define STAGE_BYTES (4 * MAT_BYTES)     // 40960
#define NSTG  4

__global__ __launch_bounds__(256, 1)
void gemm_bf16x3_kernel(const __nv_bfloat16* __restrict__ Ah,
                        const __nv_bfloat16* __restrict__ Al,
                        const __nv_bfloat16* __restrict__ Bh,
                        const __nv_bfloat16* __restrict__ Bl,
                        const float* __restrict__ bias,
                        float* __restrict__ C) {
    extern __shared__ char smem[];
    uint32_t sbase = smem_u32(smem);
    int tid = threadIdx.x, wid = tid >> 5, lane = tid & 31;
    int brow = blockIdx.y * 128;
    int bcol = blockIdx.x * 128;
    int m_off = (wid & 1) * 64;
    int n_off = (wid >> 1) * 32;

    auto load_stage = [&](int kt, int st) {
        uint32_t sb = sbase + st * STAGE_BYTES;
        int kk = kt * BKG;
#pragma unroll
        for (int i = tid; i < 512; i += 256) {
            int r = i >> 2;
            int c = (i & 3) * 16;   // byte offset within 64B of row data
            uint32_t so = (uint32_t)(r * (RS * 2)) + c;
            const char* pAh = (const char*)(Ah + (size_t)(brow + r) * HID + kk) + c;
            const char* pAl = (const char*)(Al + (size_t)(brow + r) * HID + kk) + c;
            const char* pBh = (const char*)(Bh + (size_t)(bcol + r) * HID + kk) + c;
            const char* pBl = (const char*)(Bl + (size_t)(bcol + r) * HID + kk) + c;
            CP_ASYNC16(sb + OFF_AH + so, pAh);
            CP_ASYNC16(sb + OFF_AL + so, pAl);
            CP_ASYNC16(sb + OFF_BH + so, pBh);
            CP_ASYNC16(sb + OFF_BL + so, pBl);
        }
    };

    float acc[4][4][4];
#pragma unroll
    for (int f = 0; f < 4; f++)
#pragma unroll
        for (int n = 0; n < 4; n++)
#pragma unroll
            for (int j = 0; j < 4; j++) acc[f][n][j] = 0.f;

    load_stage(0, 0); CP_COMMIT();
    load_stage(1, 1); CP_COMMIT();
    load_stage(2, 2); CP_COMMIT();

    // per-thread ldmatrix row/col within a frag: row = lane%16, colhalf = lane/16
    uint32_t lrow = (uint32_t)(lane & 15) * (RS * 2) + (uint32_t)(lane >> 4) * 16;

    for (int kt = 0; kt < KTN; kt++) {
        CP_WAIT(2);
        __syncthreads();
        uint32_t sb = sbase + (kt & 3) * STAGE_BYTES;
#pragma unroll
        for (int ks = 0; ks < 2; ks++) {
            uint32_t kb = (uint32_t)(ks * 32);  // 16 bf16 = 32 bytes
            uint32_t ah[4][4], al[4][4], bh[2][4], bl[2][4];
#pragma unroll
            for (int f = 0; f < 4; f++) {
                uint32_t a = sb + OFF_AH + (uint32_t)((m_off + f * 16) * (RS * 2)) + kb + lrow;
                LDSM_X4(ah[f][0], ah[f][1], ah[f][2], ah[f][3], a);
            }
#pragma unroll
            for (int p = 0; p < 2; p++) {
                uint32_t b = sb + OFF_BH + (uint32_t)((n_off + p * 16) * (RS * 2)) + kb + lrow;
                LDSM_X4(bh[p][0], bh[p][1], bh[p][2], bh[p][3], b);
            }
            // term 1: Ah * Bh
#pragma unroll
            for (int f = 0; f < 4; f++)
#pragma unroll
                for (int p = 0; p < 2; p++) {
                    MMA16816(acc[f][2 * p],     ah[f], bh[p][0], bh[p][2]);
                    MMA16816(acc[f][2 * p + 1], ah[f], bh[p][1], bh[p][3]);
                }
            // term 2: Ah * Bl
#pragma unroll
            for (int p = 0; p < 2; p++) {
                uint32_t b = sb + OFF_BL + (uint32_t)((n_off + p * 16) * (RS * 2)) + kb + lrow;
                LDSM_X4(bl[p][0], bl[p][1], bl[p][2], bl[p][3], b);
            }
#pragma unroll
            for (int f = 0; f < 4; f++)
#pragma unroll
                for (int p = 0; p < 2; p++) {
                    MMA16816(acc[f][2 * p],     ah[f], bl[p][0], bl[p][2]);
                    MMA16816(acc[f][2 * p + 1], ah[f], bl[p][1], bl[p][3]);
                }
            // term 3: Al * Bh
#pragma unroll
            for (int f = 0; f < 4; f++) {
                uint32_t a = sb + OFF_AL + (uint32_t)((m_off + f * 16) * (RS * 2)) + kb + lrow;
                LDSM_X4(al[f][0], al[f][1], al[f][2], al[f][3], a);
            }
#pragma unroll
            for (int f = 0; f < 4; f++)
#pragma unroll
                for (int p = 0; p < 2; p++) {
                    MMA16816(acc[f][2 * p],     al[f], bh[p][0], bh[p][2]);
                    MMA16816(acc[f][2 * p + 1], al[f], bh[p][1], bh[p][3]);
                }
        }
        if (kt + 3 < KTN) load_stage(kt + 3, (kt + 3) & 3);
        CP_COMMIT();  // always commit (possibly empty) so wait_group counts stay exact
    }

    // epilogue: acc[f][n]: rows m_off+f*16 + lane/4 (+8), cols n_off+n*8 + (lane%4)*2
#pragma unroll
    for (int f = 0; f < 4; f++) {
        int r0 = brow + m_off + f * 16 + (lane >> 2);
#pragma unroll
        for (int n = 0; n < 4; n++) {
            int c = bcol + n_off + n * 8 + (lane & 3) * 2;
            float b0 = 0.f, b1 = 0.f;
            if (bias) { b0 = bias[c]; b1 = bias[c + 1]; }
            float2 v0 = make_float2(acc[f][n][0] + b0, acc[f][n][1] + b1);
            float2 v1 = make_float2(acc[f][n][2] + b0, acc[f][n][3] + b1);
            *reinterpret_cast<float2*>(C + (size_t)r0 * HID + c) = v0;
            *reinterpret_cast<float2*>(C + (size_t)(r0 + 8) * HID + c) = v1;
        }
    }
}

// ===================== alpha projections =====================================
__global__ void alpha_kernel(const float* __restrict__ xw,
                             const float* __restrict__ a_s,
                             const float* __restrict__ a_d,
                             float* __restrict__ asrc, float* __restrict__ adst) {
    int gw = blockIdx.x * (blockDim.x >> 5) + (threadIdx.x >> 5);
    if (gw >= NND * HH) return;
    int t = threadIdx.x & 31;
    int n = gw >> 2, h = gw & 3;
    const float* row = xw + (size_t)n * HID + h * DD;
    const float* vs = a_s + h * DD;
    const float* vd = a_d + h * DD;
    float ss = 0.f, sd = 0.f;
#pragma unroll
    for (int k = 0; k < 6; k++) {
        float v = row[t + 32 * k];
        ss = fmaf(v, vs[t + 32 * k], ss);
        sd = fmaf(v, vd[t + 32 * k], sd);
    }
#pragma unroll
    for (int o = 16; o; o >>= 1) {
        ss += __shfl_xor_sync(0xffffffffu, ss, o);
        sd += __shfl_xor_sync(0xffffffffu, sd, o);
    }
    if (t == 0) {
        asrc[n * HH + h] = ss;
        adst[n * HH + h] = sd;
    }
}

__device__ __forceinline__ float lrelu(float x) {
    return x > 0.f ? x : NSLOPE * x;
}

// ============ fused aggregation + bias + LN + ReLU + residual (+bf16 out) ====
__global__ __launch_bounds__(256)
void agg_kernel(const int* __restrict__ rowptr, const int* __restrict__ esrc,
                const float* __restrict__ asrc, const float* __restrict__ adst,
                const float* __restrict__ xw, const float* __restrict__ h_in,
                const float* __restrict__ bias, const float* __restrict__ gamma,
                const float* __restrict__ beta, float* __restrict__ h_out,
                __nv_bfloat16* __restrict__ oh, __nv_bfloat16* __restrict__ ol) {
    int i = blockIdx.x * (blockDim.x >> 5) + (threadIdx.x >> 5);
    if (i >= NND) return;
    int t = threadIdx.x & 31;

    float4 ad = reinterpret_cast<const float4*>(adst)[i];
    int beg = rowptr[i], end = rowptr[i + 1];

    float m0 = -1e30f, m1 = -1e30f, m2 = -1e30f, m3 = -1e30f;
    for (int b0 = beg; b0 < end; b0 += 32) {
        int e = b0 + t;
        float l0 = -1e30f, l1 = -1e30f, l2 = -1e30f, l3 = -1e30f;
        if (e < end) {
            int j = esrc[e];
            float4 as = reinterpret_cast<const float4*>(asrc)[j];
            l0 = lrelu(as.x + ad.x); l1 = lrelu(as.y + ad.y);
            l2 = lrelu(as.z + ad.z); l3 = lrelu(as.w + ad.w);
        }
        m0 = fmaxf(m0, l0); m1 = fmaxf(m1, l1);
        m2 = fmaxf(m2, l2); m3 = fmaxf(m3, l3);
    }
#pragma unroll
    for (int o = 16; o; o >>= 1) {
        m0 = fmaxf(m0, __shfl_xor_sync(0xffffffffu, m0, o));
        m1 = fmaxf(m1, __shfl_xor_sync(0xffffffffu, m1, o));
        m2 = fmaxf(m2, __shfl_xor_sync(0xffffffffu, m2, o));
        m3 = fmaxf(m3, __shfl_xor_sync(0xffffffffu, m3, o));
    }

    float acc[24];
#pragma unroll
    for (int k = 0; k < 24; k++) acc[k] = 0.f;
    float d0 = 0.f, d1 = 0.f, d2 = 0.f, d3 = 0.f;

    for (int b0 = beg; b0 < end; b0 += 32) {
        int e = b0 + t;
        int j = 0;
        float e0 = 0.f, e1 = 0.f, e2 = 0.f, e3 = 0.f;
        if (e < end) {
            j = esrc[e];
            float4 as = reinterpret_cast<const float4*>(asrc)[j];
            e0 = expf(lrelu(as.x + ad.x) - m0);
            e1 = expf(lrelu(as.y + ad.y) - m1);
            e2 = expf(lrelu(as.z + ad.z) - m2);
            e3 = expf(lrelu(as.w + ad.w) - m3);
        }
        d0 += e0; d1 += e1; d2 += e2; d3 += e3;
        int cnt = min(32, end - b0);
        for (int q = 0; q < cnt; q++) {
            int   jq = __shfl_sync(0xffffffffu, j,  q);
            float w0 = __shfl_sync(0xffffffffu, e0, q);
            float w1 = __shfl_sync(0xffffffffu, e1, q);
            float w2 = __shfl_sync(0xffffffffu, e2, q);
            float w3 = __shfl_sync(0xffffffffu, e3, q);
            const float* row = xw + (size_t)jq * HID;
#pragma unroll
            for (int k = 0; k < 24; k++) {
                float wk = (k < 6) ? w0 : (k < 12) ? w1 : (k < 18) ? w2 : w3;
                acc[k] = fmaf(wk, row[t + 32 * k], acc[k]);
            }
        }
    }
#pragma unroll
    for (int o = 16; o; o >>= 1) {
        d0 += __shfl_xor_sync(0xffffffffu, d0, o);
        d1 += __shfl_xor_sync(0xffffffffu, d1, o);
        d2 += __shfl_xor_sync(0xffffffffu, d2, o);
        d3 += __shfl_xor_sync(0xffffffffu, d3, o);
    }
    float i0 = 1.f / d0, i1 = 1.f / d1, i2 = 1.f / d2, i3 = 1.f / d3;

    float s = 0.f;
#pragma unroll
    for (int k = 0; k < 24; k++) {
        float ik = (k < 6) ? i0 : (k < 12) ? i1 : (k < 18) ? i2 : i3;
        float v = acc[k] * ik + bias[t + 32 * k];
        acc[k] = v;
        s += v;
    }
#pragma unroll
    for (int o = 16; o; o >>= 1) s += __shfl_xor_sync(0xffffffffu, s, o);
    float mu = s * (1.f / HID);
    float vs = 0.f;
#pragma unroll
    for (int k = 0; k < 24; k++) {
        float dlt = acc[k] - mu;
        vs = fmaf(dlt, dlt, vs);
    }
#pragma unroll
    for (int o = 16; o; o >>= 1) vs += __shfl_xor_sync(0xffffffffu, vs, o);
    float rstd = rsqrtf(vs * (1.f / HID) + EPSL);

    const float* hrow = h_in + (size_t)i * HID;
    float* orow = h_out + (size_t)i * HID;
#pragma unroll
    for (int k = 0; k < 24; k++) {
        int d = t + 32 * k;
        float v = (acc[k] - mu) * rstd * gamma[d] + beta[d];
        v = fmaxf(v, 0.f) + hrow[d];
        orow[d] = v;
        if (oh) {
            __nv_bfloat16 h = __float2bfloat16(v);
            oh[(size_t)i * HID + d] = h;
            ol[(size_t)i * HID + d] = __float2bfloat16(v - __bfloat162float(h));
        }
    }
}

// ===================== graph pooling =========================================
__global__ void graph_off_kernel(const int* __restrict__ bvec, int* off) {
    int b = blockIdx.x * blockDim.x + threadIdx.x;
    if (b > BB) return;
    int lo = 0, hi = NND;
    while (lo < hi) {
        int mid = (lo + hi) >> 1;
        if (bvec[mid] < b) lo = mid + 1; else hi = mid;
    }
    off[b] = lo;
}

__global__ void pool_kernel(const float* __restrict__ h, const int* __restrict__ off,
                            float* __restrict__ pooled) {
    int b = blockIdx.x;
    int t = threadIdx.x;  // 256
    int s = off[b], e = off[b + 1];
    float a0 = 0.f, a1 = 0.f, a2 = 0.f;
    for (int n = s; n < e; n++) {
        const float* r = h + (size_t)n * HID;
        a0 += r[t];
        a1 += r[t + 256];
        a2 += r[t + 512];
    }
    float inv = 1.f / fmaxf((float)(e - s), 1.f);
    pooled[b * HID + t]       = a0 * inv;
    pooled[b * HID + t + 256] = a1 * inv;
    pooled[b * HID + t + 512] = a2 * inv;
}

// ===================== launch ================================================
extern "C" void kernel_launch(void* const* d_in, const int* in_sizes, int n_in,
                              void* d_out, int out_size) {
    const float* x      = (const float*)d_in[0];
    const int*   ei     = (const int*)d_in[1];
    const int*   bvec   = (const int*)d_in[2];
    const float* W      = (const float*)d_in[3];
    const float* attS   = (const float*)d_in[4];
    const float* attD   = (const float*)d_in[5];
    const float* bias   = (const float*)d_in[6];
    const float* gamma  = (const float*)d_in[7];
    const float* beta   = (const float*)d_in[8];
    const float* out_w  = (const float*)d_in[9];
    const float* out_b  = (const float*)d_in[10];
    float* out = (float*)d_out;

    float *xw, *h1, *h2, *asrc, *adst, *pool;
    __nv_bfloat16 *ah, *al, *wth, *wtl;
    int *deg, *rowptr, *wptr, *esrc, *off;
    cudaGetSymbolAddress((void**)&xw,    g_xw);
    cudaGetSymbolAddress((void**)&h1,    g_h1);
    cudaGetSymbolAddress((void**)&h2,    g_h2);
    cudaGetSymbolAddress((void**)&ah,    g_ah);
    cudaGetSymbolAddress((void**)&al,    g_al);
    cudaGetSymbolAddress((void**)&wth,   g_wth);
    cudaGetSymbolAddress((void**)&wtl,   g_wtl);
    cudaGetSymbolAddress((void**)&asrc,  g_asrc);
    cudaGetSymbolAddress((void**)&adst,  g_adst);
    cudaGetSymbolAddress((void**)&deg,   g_deg);
    cudaGetSymbolAddress((void**)&rowptr,g_rowptr);
    cudaGetSymbolAddress((void**)&wptr,  g_wptr);
    cudaGetSymbolAddress((void**)&esrc,  g_esrc);
    cudaGetSymbolAddress((void**)&off,   g_off);
    cudaGetSymbolAddress((void**)&pool,  g_pool);

    cudaFuncSetAttribute(gemm_bf16x3_kernel,
                         cudaFuncAttributeMaxDynamicSharedMemorySize,
                         NSTG * STAGE_BYTES);

    // CSR build
    zero_deg_kernel<<<NND / 256, 256>>>(deg);
    count_deg_kernel<<<(E2 + 255) / 256, 256>>>(ei, deg);
    scan_deg_kernel<<<1, 1024>>>(deg, rowptr, wptr);
    fill_src_kernel<<<(E2 + 255) / 256, 256>>>(ei, wptr, esrc);

    // weight transpose + split (3 matrices)
    dim3 wtG(HID / 32, HID / 32), wtB(32, 8);
    wtrans_kernel<<<wtG, wtB>>>(W,               wth,               wtl);
    wtrans_kernel<<<wtG, wtB>>>(W + HID * HID,   wth + HID * HID,   wtl + HID * HID);
    wtrans_kernel<<<wtG, wtB>>>(out_w,           wth + 2 * HID * HID, wtl + 2 * HID * HID);

    int alphaBlocks = (NND * HH) / 8;
    int aggBlocks   = NND / 8;
    dim3 gBig(HID / 128, NND / 128);   // (6, 512)
    size_t smemSz = NSTG * STAGE_BYTES;

    // layer 0
    convert_hilo_kernel<<<(NND * HID / 4 + 255) / 256, 256>>>(x, ah, al, NND * HID / 4);
    gemm_bf16x3_kernel<<<gBig, 256, smemSz>>>(ah, al, wth, wtl, nullptr, xw);
    alpha_kernel<<<alphaBlocks, 256>>>(xw, attS, attD, asrc, adst);
    agg_kernel<<<aggBlocks, 256>>>(rowptr, esrc, asrc, adst, xw, x,
                                   bias, gamma, beta, h1, ah, al);  // emits bf16 h1
    // layer 1
    gemm_bf16x3_kernel<<<gBig, 256, smemSz>>>(ah, al, wth + HID * HID,
                                              wtl + HID * HID, nullptr, xw);
    alpha_kernel<<<alphaBlocks, 256>>>(xw, attS + HH * DD, attD + HH * DD, asrc, adst);
    agg_kernel<<<aggBlocks, 256>>>(rowptr, esrc, asrc, adst, xw, h1,
                                   bias + HID, gamma + HID, beta + HID, h2,
                                   nullptr, nullptr);

    // pooling + output projection
    graph_off_kernel<<<(BB + 1 + 255) / 256, 256>>>(bvec, off);
    pool_kernel<<<BB, 256>>>(h2, off, pool);
    convert_hilo_kernel<<<(BB * HID / 4 + 255) / 256, 256>>>(pool, ah, al, BB * HID / 4);
    dim3 gOut(HID / 128, BB / 128);    // (6, 16)
    gemm_bf16x3_kernel<<<gOut, 256, smemSz>>>(ah, al, wth + 2 * HID * HID,
                                              wtl + 2 * HID * HID, out_b, out);
}